// round 8
// baseline (speedup 1.0000x reference)
#include <cuda_runtime.h>

#define N_PTS 64
#define NA 67   // n + 3
#define NC 69   // augmented columns (NA + 2 RHS)

// Solved TPS weights: w[i*2 + c]; rows 0..63 kernel weights, 64..66 affine.
__device__ float    g_w[NA * 2];
__device__ unsigned g_flag;     // 0 at module load; set once weights are ready

// Shared memory: solve scratch and eval tables overlap (solve only in block 0,
// and block 0 reuses the region for eval after its internal barrier).
struct SolveShm {
    float M[NA][NC];     // stride 69 (odd) -> conflict-free
    float pcol[2][NA];   // pivot-column values, double-buffered
    int   prs[NA];
};
struct EvalShm {
    float2             sp[N_PTS];
    unsigned long long sw[N_PTS];
    float              aff[6];
};

__device__ __forceinline__ float fsqrt_approx(float x) {
    float r;
    asm("sqrt.approx.f32 %0, %1;" : "=f"(r) : "f"(x));
    return r;
}
__device__ __forceinline__ unsigned long long pack2(float lo, float hi) {
    unsigned long long r;
    asm("mov.b64 %0, {%1, %2};" : "=l"(r) : "f"(lo), "f"(hi));
    return r;
}
__device__ __forceinline__ void unpack2(unsigned long long v, float& lo, float& hi) {
    asm("mov.b64 {%0, %1}, %2;" : "=f"(lo), "=f"(hi) : "l"(v));
}

// ---------------------------------------------------------------------------
// Solve phase (block 0 only): fp32 Gauss-Jordan, implicit partial pivoting.
// 512 threads = 64 rows x 8 lanes; rows 64..66 secondary on threads 0..23.
// One barrier per iteration (double-buffered pcol); redundant per-warp REDUX
// pivot search; pivot value via register shuffle.
// ---------------------------------------------------------------------------
__device__ void tps_solve(SolveShm* S,
                          const float* __restrict__ pts,
                          const float* __restrict__ vals)
{
    const int tid  = threadIdx.x;
    const int nt   = blockDim.x;
    const int lane = tid & 31;

    // Build augmented matrix [[K, B, Y],[B^T, 0, 0]] in fp32
    for (int idx = tid; idx < NA * NC; idx += nt) {
        int i = idx / NC, j = idx % NC;
        float v = 0.0f;
        if (i < N_PTS) {
            if (j < N_PTS) {
                float dx = pts[2*i]   - pts[2*j];
                float dy = pts[2*i+1] - pts[2*j+1];
                v = sqrtf(fmaf(dx, dx, dy*dy));
            } else if (j < NA) {
                int k = j - N_PTS;
                v = (k == 0) ? 1.0f : pts[2*i + (k-1)];
            } else {
                v = vals[2*i + (j - NA)];
            }
        } else if (j < N_PTS) {
            int k = i - N_PTS;
            v = (k == 0) ? 1.0f : pts[2*j + (k-1)];
        }
        S->M[i][j] = v;
        if (j == 0) S->pcol[0][i] = v;
    }
    __syncthreads();

    const int er  = tid >> 3;           // primary row (0..63)
    const int ec  = tid & 7;            // column lane (0..7)
    const bool has2 = (tid < 24);       // threads 0..23 own rows 64..66
    const int er2 = 64 + (tid >> 3);    // valid when has2

    // search rows (lane-based; identical across warps)
    const int r0 = lane, r1 = lane + 32, r2 = lane + 64;
    const bool r2ok = (r2 < NA);
    unsigned pm0 = 0, pm1 = 0, pm2 = 0;   // pivoted-row masks (warp-uniform)

    int cur = 0;
    for (int k = 0; k < NA; k++) {
        const int nxt = cur ^ 1;

        // ---- phase A: reads of pcol[cur] only ----
        const float v0 = S->pcol[cur][r0];
        const float v1 = S->pcol[cur][r1];
        const float v2 = r2ok ? S->pcol[cur][r2] : 0.0f;
        const float fnum  = S->pcol[cur][er];
        const float fnum2 = has2 ? S->pcol[cur][er2] : 0.0f;

        unsigned key = 0;
        {
            unsigned b = (__float_as_uint(v0) & 0x7FFFFF80u) | (unsigned)r0;
            if (!((pm0 >> lane) & 1u)) key = b;
        }
        {
            unsigned b = (__float_as_uint(v1) & 0x7FFFFF80u) | (unsigned)r1;
            if (!((pm1 >> lane) & 1u) && b > key) key = b;
        }
        if (r2ok) {
            unsigned b = (__float_as_uint(v2) & 0x7FFFFF80u) | (unsigned)r2;
            if (!((pm2 >> lane) & 1u) && b > key) key = b;
        }
        key = __reduce_max_sync(0xFFFFFFFFu, key);
        const int pr = (int)(key & 0x7Fu);
        if (pr < 32)       pm0 |= 1u << pr;
        else if (pr < 64)  pm1 |= 1u << (pr - 32);
        else               pm2 |= 1u << (pr - 64);
        if (tid == 0) S->prs[k] = pr;

        const int slot = pr >> 5;
        float cand = (slot == 0) ? v0 : ((slot == 1) ? v1 : v2);
        const float piv = __shfl_sync(0xFFFFFFFFu, cand, pr & 31);
        const float invpiv = __fdividef(1.0f, piv);

        const float f    = fnum  * invpiv;
        const bool  act  = (er  != pr);

        // ---- phase B: writes to M (rows != pr) and pcol[nxt] ----
        {
            int j = k + 1 + ec;
            if (j < NC) {
                float mv = S->M[er][j];
                float v  = fmaf(-f, S->M[pr][j], mv);
                if (act) S->M[er][j] = v;
                if (ec == 0) S->pcol[nxt][er] = act ? v : mv;
                for (j += 8; j < NC; j += 8) {
                    if (act) S->M[er][j] = fmaf(-f, S->M[pr][j], S->M[er][j]);
                }
            }
        }
        if (has2) {
            const float f2   = fnum2 * invpiv;
            const bool  act2 = (er2 != pr);
            int j = k + 1 + ec;
            if (j < NC) {
                float mv = S->M[er2][j];
                float v  = fmaf(-f2, S->M[pr][j], mv);
                if (act2) S->M[er2][j] = v;
                if (ec == 0) S->pcol[nxt][er2] = act2 ? v : mv;
                for (j += 8; j < NC; j += 8) {
                    if (act2) S->M[er2][j] = fmaf(-f2, S->M[pr][j], S->M[er2][j]);
                }
            }
        }
        __syncthreads();
        cur = nxt;
    }

    // extract: w_k = M[pr_k][rhs] / M[pr_k][k]
    if (tid < NA) {
        int pr = S->prs[tid];
        float inv = 1.0f / S->M[pr][tid];
        g_w[tid*2]   = S->M[pr][NA]   * inv;
        g_w[tid*2+1] = S->M[pr][NA+1] * inv;
    }
    __syncthreads();
}

// ---------------------------------------------------------------------------
// Fused kernel: block 0 solves then publishes; all blocks evaluate.
// grid 512 x block 512, 4 x-adjacent pixels per thread.
// ---------------------------------------------------------------------------
__global__ void __launch_bounds__(512) tps_fused_kernel(
    const float* __restrict__ pts, const float* __restrict__ vals,
    float* __restrict__ out)
{
    __shared__ char shm_raw[sizeof(SolveShm)];
    const int tid = threadIdx.x;

    if (blockIdx.x == 0) {
        tps_solve(reinterpret_cast<SolveShm*>(shm_raw), pts, vals);
        if (tid == 0) {
            asm volatile("st.release.gpu.global.u32 [%0], %1;"
                         :: "l"(&g_flag), "r"(1u) : "memory");
        }
        __syncthreads();   // reuse shm for eval below
    } else {
        if (tid == 0) {
            unsigned v = 0;
            do {
                asm volatile("ld.acquire.gpu.global.u32 %0, [%1];"
                             : "=r"(v) : "l"(&g_flag) : "memory");
                if (!v) __nanosleep(128);
            } while (!v);
        }
        __syncthreads();
    }

    // ---------------- eval phase (all blocks) ----------------
    EvalShm* E = reinterpret_cast<EvalShm*>(shm_raw);
    if (tid < N_PTS) {
        E->sp[tid] = make_float2(pts[2*tid], pts[2*tid+1]);
        E->sw[tid] = pack2(g_w[2*tid], g_w[2*tid+1]);
    }
    if (tid < 6) E->aff[tid] = g_w[2*N_PTS + tid];
    __syncthreads();

    const int gid = blockIdx.x * blockDim.x + tid;   // 0 .. 262143
    const int x0  = (gid & 255) << 2;
    const int y   = gid >> 8;

    const float fy = (float)y;
    float fx[4];
    #pragma unroll
    for (int j = 0; j < 4; j++) fx[j] = (float)(x0 + j);

    unsigned long long acc[4];
    #pragma unroll
    for (int j = 0; j < 4; j++) {
        float a0 = fmaf(E->aff[2], fx[j], fmaf(E->aff[4], fy, E->aff[0]));
        float a1 = fmaf(E->aff[3], fx[j], fmaf(E->aff[5], fy, E->aff[1]));
        acc[j] = pack2(a0, a1);
    }

    #pragma unroll 16
    for (int i = 0; i < N_PTS; i++) {
        float2 p = E->sp[i];
        unsigned long long wv = E->sw[i];
        float dy  = fy - p.y;
        float dy2 = dy * dy;
        #pragma unroll
        for (int j = 0; j < 4; j++) {
            float dx = fx[j] - p.x;
            float d2 = fmaf(dx, dx, dy2);
            float d  = fsqrt_approx(d2);
            unsigned long long dd = pack2(d, d);
            asm("fma.rn.f32x2 %0, %1, %2, %0;" : "+l"(acc[j]) : "l"(dd), "l"(wv));
        }
    }

    float4 o0, o1;
    unpack2(acc[0], o0.x, o0.y);
    unpack2(acc[1], o0.z, o0.w);
    unpack2(acc[2], o1.x, o1.y);
    unpack2(acc[3], o1.z, o1.w);
    float4* outv = reinterpret_cast<float4*>(out);
    outv[gid*2]   = o0;
    outv[gid*2+1] = o1;
}

// ---------------------------------------------------------------------------
extern "C" void kernel_launch(void* const* d_in, const int* in_sizes, int n_in,
                              void* d_out, int out_size)
{
    const float* pts  = (const float*)d_in[0];
    const float* vals = (const float*)d_in[1];
    float* out = (float*)d_out;

    tps_fused_kernel<<<512, 512>>>(pts, vals, out);
}

// round 9
// speedup vs baseline: 1.1486x; 1.1486x over previous
#include <cuda_runtime.h>

#define N_PTS 64
#define NA 67   // n + 3
#define NC 69   // augmented columns (NA + 2 RHS)

// Solved TPS weights: w[i*2 + c]; rows 0..63 kernel weights, 64..66 affine.
__device__ float g_w[NA * 2];

// ---------------------------------------------------------------------------
// Blocked (lookahead-4) fp32 Gauss-Jordan with implicit partial pivoting.
// 544 threads = 68 rows x 8 col-lanes. 17 barrier-rounds (16x PW=4 + 1x PW=3).
// Phase A (warp-redundant, registers): 4 sequential pivot searches over the
//   round's columns, with within-round rank-1 updates applied to lane-mapped
//   candidate registers. Produces pivot rows prs[], inter-pivot coefficients
//   fp[t][s], and per-own-row multipliers fown[].
// Phase B: fused rank-4 trailing update, M double-buffered (read cur/write nxt)
//   -> ONE __syncthreads per round, no read/write hazards.
// ---------------------------------------------------------------------------

template<int PW>
__device__ __forceinline__ void gj_round(
    const float (*__restrict__ Mc)[NC], float (*__restrict__ Mn)[NC],
    int k0, int er, int ec, bool row_ok, int lane, int tid,
    unsigned& pm0, unsigned& pm1, unsigned& pm2,
    float* __restrict__ s_inv, int* __restrict__ s_prs)
{
    const int r0 = lane, r1 = lane + 32, r2 = lane + 64;
    const bool r2ok = (r2 < NA);

    // candidate values of the round's PW columns (lane-mapped rows)
    float c0[PW], c1[PW], c2[PW], own[PW];
    #pragma unroll
    for (int c = 0; c < PW; c++) {
        c0[c]  = Mc[r0][k0 + c];
        c1[c]  = Mc[r1][k0 + c];
        c2[c]  = r2ok ? Mc[r2][k0 + c] : 0.0f;
        own[c] = Mc[row_ok ? er : 0][k0 + c];
    }

    float fh0[PW], fh1[PW], fh2[PW];   // candidate multiplier history
    float fown[PW];                    // this thread's row multipliers
    int   prs[PW];                     // pivot rows this round
    float fp[PW][PW];                  // fp[t][s]: pivot-row-t coeff vs pivot s

    #pragma unroll
    for (int t = 0; t < PW; t++) {
        // ---- pivot search over unpivoted rows (magnitude-encoded REDUX) ----
        unsigned key = 0;
        {
            unsigned b = (__float_as_uint(c0[t]) & 0x7FFFFF80u) | (unsigned)r0;
            if (!((pm0 >> lane) & 1u)) key = b;
        }
        {
            unsigned b = (__float_as_uint(c1[t]) & 0x7FFFFF80u) | (unsigned)r1;
            if (!((pm1 >> lane) & 1u) && b > key) key = b;
        }
        if (r2ok) {
            unsigned b = (__float_as_uint(c2[t]) & 0x7FFFFF80u) | (unsigned)r2;
            if (!((pm2 >> lane) & 1u) && b > key) key = b;
        }
        key = __reduce_max_sync(0xFFFFFFFFu, key);
        const int pr = (int)(key & 0x7Fu);
        prs[t] = pr;
        if (pr < 32)      pm0 |= 1u << pr;
        else if (pr < 64) pm1 |= 1u << (pr - 32);
        else              pm2 |= 1u << (pr - 64);

        const int slot = pr >> 5;
        const int pl   = pr & 31;

        // pivot value from the owning lane's candidate register
        float pivc = (slot == 0) ? c0[t] : ((slot == 1) ? c1[t] : c2[t]);
        const float piv = __shfl_sync(0xFFFFFFFFu, pivc, pl);
        const float inv = __fdividef(1.0f, piv);
        if (tid == 0) { s_inv[k0 + t] = inv; s_prs[k0 + t] = pr; }

        // pivot row's remaining-column values (as of sub-step t)
        float urow[PW];
        #pragma unroll
        for (int c = t + 1; c < PW; c++) {
            float uc = (slot == 0) ? c0[c] : ((slot == 1) ? c1[c] : c2[c]);
            urow[c] = __shfl_sync(0xFFFFFFFFu, uc, pl);
        }
        // inter-pivot coefficients: fp[t][s] = multiplier history of row pr
        #pragma unroll
        for (int s = 0; s < t; s++) {
            float fhv = (slot == 0) ? fh0[s] : ((slot == 1) ? fh1[s] : fh2[s]);
            fp[t][s] = __shfl_sync(0xFFFFFFFFu, fhv, pl);
        }

        // multipliers (0 for the pivot row itself: no self-elimination)
        float f0 = (r0 == pr)          ? 0.0f : c0[t] * inv;
        float f1 = (r1 == pr)          ? 0.0f : c1[t] * inv;
        float f2 = (!r2ok || r2 == pr) ? 0.0f : c2[t] * inv;
        float fo = (!row_ok || er == pr) ? 0.0f : own[t] * inv;
        fh0[t] = f0; fh1[t] = f1; fh2[t] = f2; fown[t] = fo;

        // apply rank-1 update to the remaining in-round columns (registers)
        #pragma unroll
        for (int c = t + 1; c < PW; c++) {
            c0[c]  = fmaf(-f0, urow[c], c0[c]);
            c1[c]  = fmaf(-f1, urow[c], c1[c]);
            c2[c]  = fmaf(-f2, urow[c], c2[c]);
            own[c] = fmaf(-fo, urow[c], own[c]);
        }
    }

    // ---- phase B: fused rank-PW trailing update, Mc -> Mn ----
    if (row_ok) {
        for (int j = k0 + PW + ec; j < NC; j += 8) {
            float u[PW];
            #pragma unroll
            for (int t = 0; t < PW; t++) {
                float v = Mc[prs[t]][j];
                #pragma unroll
                for (int s = 0; s < t; s++) v = fmaf(-fp[t][s], u[s], v);
                u[t] = v;
            }
            float nv = Mc[er][j];
            #pragma unroll
            for (int t = 0; t < PW; t++) nv = fmaf(-fown[t], u[t], nv);
            Mn[er][j] = nv;
        }
    }
}

__global__ void __launch_bounds__(544) tps_solve_kernel(
    const float* __restrict__ pts, const float* __restrict__ vals)
{
    __shared__ float M[2][NA][NC];   // double-buffered; stride 69 (odd)
    __shared__ float s_inv[NA];
    __shared__ int   s_prs[NA];

    const int tid  = threadIdx.x;
    const int nt   = blockDim.x;
    const int lane = tid & 31;

    // Build augmented matrix [[K, B, Y],[B^T, 0, 0]] in fp32, into buffer 0
    for (int idx = tid; idx < NA * NC; idx += nt) {
        int i = idx / NC, j = idx % NC;
        float v = 0.0f;
        if (i < N_PTS) {
            if (j < N_PTS) {
                float dx = pts[2*i]   - pts[2*j];
                float dy = pts[2*i+1] - pts[2*j+1];
                v = sqrtf(fmaf(dx, dx, dy*dy));
            } else if (j < NA) {
                int k = j - N_PTS;
                v = (k == 0) ? 1.0f : pts[2*i + (k-1)];
            } else {
                v = vals[2*i + (j - NA)];
            }
        } else if (j < N_PTS) {
            int k = i - N_PTS;
            v = (k == 0) ? 1.0f : pts[2*j + (k-1)];
        }
        M[0][i][j] = v;
    }
    __syncthreads();

    const int er = tid >> 3;            // row (0..67; 67 idle)
    const int ec = tid & 7;             // column lane (0..7)
    const bool row_ok = (er < NA);
    unsigned pm0 = 0, pm1 = 0, pm2 = 0; // pivoted-row masks (thread-uniform)

    int cur = 0;
    #pragma unroll 1
    for (int r = 0; r < 16; r++) {
        gj_round<4>(M[cur], M[cur ^ 1], r * 4, er, ec, row_ok, lane, tid,
                    pm0, pm1, pm2, s_inv, s_prs);
        __syncthreads();
        cur ^= 1;
    }
    gj_round<3>(M[cur], M[cur ^ 1], 64, er, ec, row_ok, lane, tid,
                pm0, pm1, pm2, s_inv, s_prs);
    __syncthreads();
    cur ^= 1;

    // extraction: w_k = RHS_final[pr_k] * (1/diag_k)
    if (tid < NA) {
        int pr = s_prs[tid];
        float inv = s_inv[tid];
        g_w[tid*2]   = M[cur][pr][NA]   * inv;
        g_w[tid*2+1] = M[cur][pr][NA+1] * inv;
    }
}

// ---------------------------------------------------------------------------
// Kernel 2: dense evaluation, 4 x-adjacent pixels per thread. (unchanged)
// ---------------------------------------------------------------------------
__device__ __forceinline__ float fsqrt_approx(float x) {
    float r;
    asm("sqrt.approx.f32 %0, %1;" : "=f"(r) : "f"(x));
    return r;
}
__device__ __forceinline__ unsigned long long pack2(float lo, float hi) {
    unsigned long long r;
    asm("mov.b64 %0, {%1, %2};" : "=l"(r) : "f"(lo), "f"(hi));
    return r;
}
__device__ __forceinline__ void unpack2(unsigned long long v, float& lo, float& hi) {
    asm("mov.b64 {%0, %1}, %2;" : "=f"(lo), "=f"(hi) : "l"(v));
}

__global__ void __launch_bounds__(256) tps_eval_kernel(
    const float* __restrict__ pts, float* __restrict__ out)
{
    __shared__ float2             sp[N_PTS];
    __shared__ unsigned long long sw[N_PTS];
    __shared__ float              aff[6];
    const int tid = threadIdx.x;

    if (tid < N_PTS) {
        sp[tid] = make_float2(pts[2*tid], pts[2*tid+1]);
        sw[tid] = pack2(g_w[2*tid], g_w[2*tid+1]);
    }
    if (tid < 6) aff[tid] = g_w[2*N_PTS + tid];
    __syncthreads();

    const int gid = blockIdx.x * blockDim.x + tid;   // 0 .. 262143
    const int x0  = (gid & 255) << 2;
    const int y   = gid >> 8;

    const float fy = (float)y;
    float fx[4];
    #pragma unroll
    for (int j = 0; j < 4; j++) fx[j] = (float)(x0 + j);

    unsigned long long acc[4];
    #pragma unroll
    for (int j = 0; j < 4; j++) {
        float a0 = fmaf(aff[2], fx[j], fmaf(aff[4], fy, aff[0]));
        float a1 = fmaf(aff[3], fx[j], fmaf(aff[5], fy, aff[1]));
        acc[j] = pack2(a0, a1);
    }

    #pragma unroll 16
    for (int i = 0; i < N_PTS; i++) {
        float2 p = sp[i];
        unsigned long long wv = sw[i];
        float dy  = fy - p.y;
        float dy2 = dy * dy;
        #pragma unroll
        for (int j = 0; j < 4; j++) {
            float dx = fx[j] - p.x;
            float d2 = fmaf(dx, dx, dy2);
            float d  = fsqrt_approx(d2);
            unsigned long long dd = pack2(d, d);
            asm("fma.rn.f32x2 %0, %1, %2, %0;" : "+l"(acc[j]) : "l"(dd), "l"(wv));
        }
    }

    float4 o0, o1;
    unpack2(acc[0], o0.x, o0.y);
    unpack2(acc[1], o0.z, o0.w);
    unpack2(acc[2], o1.x, o1.y);
    unpack2(acc[3], o1.z, o1.w);
    float4* outv = reinterpret_cast<float4*>(out);
    outv[gid*2]   = o0;
    outv[gid*2+1] = o1;
}

// ---------------------------------------------------------------------------
extern "C" void kernel_launch(void* const* d_in, const int* in_sizes, int n_in,
                              void* d_out, int out_size)
{
    const float* pts  = (const float*)d_in[0];
    const float* vals = (const float*)d_in[1];
    float* out = (float*)d_out;

    tps_solve_kernel<<<1, 544>>>(pts, vals);
    tps_eval_kernel<<<1024, 256>>>(pts, out);
}